// round 2
// baseline (speedup 1.0000x reference)
#include <cuda_runtime.h>

// SuperLinear: out[b,n] = sum_m x[b,n,m] * w1[m,0,n] + b1[0,n,0]
// Shapes: x[B=256, N=4096, M=64], w1[M=64, 1, N=4096], b1[1, N, 1], out[B, N].
//
// Pure HBM-stream on x (268 MB). Weights (1 MB) are staged per-block into
// shared memory TRANSPOSED (w_s[n_loc][m]) so both the gmem load (coalesced
// over n) and the compute-side read (within-row LDS.128) are conflict-free.
// Compute: half-warp per output — lane holds float4 of the 64-float x row
// (one warp = 2 outputs = 512B contiguous LDG.128), 4-wide FMA dot,
// 4 butterfly shuffles within the 16-lane group, lanes 0/16 store.

#define N_DIM   4096
#define M_DIM   64
#define NTILE   64          // n-values per block
#define BTILE   16          // b-values per block
#define WROW    68          // padded shared row stride (floats), 16B-aligned

__global__ __launch_bounds__(256)
void superlinear_kernel(const float* __restrict__ x,
                        const float* __restrict__ w,
                        const float* __restrict__ bias,
                        float* __restrict__ out,
                        int n_btiles) {
    __shared__ float w_s[NTILE][WROW];   // w_s[n_loc][m]
    __shared__ float b_s[NTILE];

    const int tid  = threadIdx.x;
    const int bx   = blockIdx.x;
    const int n0   = (bx & (N_DIM / NTILE - 1)) * NTILE;   // 64 n-tiles
    const int b0   = (bx / (N_DIM / NTILE)) * BTILE;

    // ---- Stage w tile (transposed) + bias into shared, coalesced over n ----
    {
        const int n_loc = tid & (NTILE - 1);   // 0..63
        const int m_hi  = tid >> 6;            // 0..3
        #pragma unroll
        for (int mb = 0; mb < M_DIM; mb += 4) {
            const int m = mb + m_hi;
            w_s[n_loc][m] = w[(size_t)m * N_DIM + n0 + n_loc];
        }
        if (tid < NTILE)
            b_s[tid] = bias[n0 + tid];
    }
    __syncthreads();

    // ---- Compute ----
    const int warp  = tid >> 5;          // 0..7
    const int lane  = tid & 31;
    const int half  = lane >> 4;         // 0 or 1
    const int sub   = lane & 15;         // position within 16-lane group

    #pragma unroll 1
    for (int bb = 0; bb < BTILE; bb++) {
        const int b = b0 + bb;
        #pragma unroll
        for (int pass = 0; pass < NTILE / 16; pass++) {     // 4 passes
            const int n_loc = pass * 16 + warp * 2 + half;  // 0..63
            const size_t row = ((size_t)b * N_DIM + n0 + n_loc);

            const float4 xv = __ldg(reinterpret_cast<const float4*>(x) + row * (M_DIM / 4) + sub);
            const float4 wv = *reinterpret_cast<const float4*>(&w_s[n_loc][sub * 4]);

            float s = xv.x * wv.x;
            s = fmaf(xv.y, wv.y, s);
            s = fmaf(xv.z, wv.z, s);
            s = fmaf(xv.w, wv.w, s);

            #pragma unroll
            for (int off = 8; off > 0; off >>= 1)
                s += __shfl_xor_sync(0xFFFFFFFFu, s, off);

            if (sub == 0)
                out[(size_t)b * N_DIM + n0 + n_loc] = s + b_s[n_loc];
        }
    }
}

extern "C" void kernel_launch(void* const* d_in, const int* in_sizes, int n_in,
                              void* d_out, int out_size) {
    const float* x    = (const float*)d_in[0];   // [B, N, 64]
    const float* w1   = (const float*)d_in[1];   // [64, 1, N]
    const float* b1   = (const float*)d_in[2];   // [1, N, 1]
    float* out        = (float*)d_out;           // [B, N]

    const int B = in_sizes[0] / (N_DIM * M_DIM); // 256
    const int n_btiles = B / BTILE;              // 16
    const int blocks = n_btiles * (N_DIM / NTILE); // 1024

    superlinear_kernel<<<blocks, 256>>>(x, w1, b1, out, n_btiles);
}